// round 15
// baseline (speedup 1.0000x reference)
#include <cuda_runtime.h>
#include <cuda_fp16.h>
#include <math.h>
#include <stdint.h>

#define BB 128
#define NN 100
#define HH 128
#define NODES (BB*NN)          // 12800
#define NODES_PAD 12864
#define PI_F 3.14159265358979323846f
#define EPS_F 1e-7f

__device__ float g_R[NODES_PAD * 9];
__device__ float g_cv[NODES_PAD * 3];
__device__ float g_hacc[NODES_PAD * HH];

typedef unsigned long long u64;

// ---- packed f32x2 helpers -------------------------------------------------
__device__ __forceinline__ u64 fma2(u64 a, u64 b, u64 c) {
    u64 d;
    asm("fma.rn.f32x2 %0, %1, %2, %3;" : "=l"(d) : "l"(a), "l"(b), "l"(c));
    return d;
}
__device__ __forceinline__ u64 add2(u64 a, u64 b) {
    u64 d; asm("add.rn.f32x2 %0, %1, %2;" : "=l"(d) : "l"(a), "l"(b)); return d;
}
__device__ __forceinline__ u64 mul2(u64 a, u64 b) {
    u64 d; asm("mul.rn.f32x2 %0, %1, %2;" : "=l"(d) : "l"(a), "l"(b)); return d;
}
__device__ __forceinline__ u64 pack2(float lo, float hi) {
    u64 d; asm("mov.b64 %0, {%1, %2};" : "=l"(d) : "f"(lo), "f"(hi)); return d;
}
__device__ __forceinline__ u64 packu(uint32_t a, uint32_t b) {
    u64 d; asm("mov.b64 %0, {%1, %2};" : "=l"(d) : "r"(a), "r"(b)); return d;
}
__device__ __forceinline__ void unpack2(u64 v, float& lo, float& hi) {
    asm("mov.b64 {%0, %1}, %2;" : "=f"(lo), "=f"(hi) : "l"(v));
}
__device__ __forceinline__ float tanh_fast(float x) {
    float r; asm("tanh.approx.f32 %0, %1;" : "=f"(r) : "f"(x)); return r;
}
// pack two f32 -> f16x2 (lo in low half)
__device__ __forceinline__ uint32_t f16x2_pack(float lo, float hi) {
    uint32_t r;
    asm("cvt.rn.f16x2.f32 %0, %1, %2;" : "=r"(r) : "f"(hi), "f"(lo));
    return r;
}

// mma.sync m16n8k16 row.col f16 -> f32 accumulate
__device__ __forceinline__ void mma_f16(float* d, const uint32_t* a,
                                        uint32_t b0, uint32_t b1) {
    asm volatile(
        "mma.sync.aligned.m16n8k16.row.col.f32.f16.f16.f32 "
        "{%0,%1,%2,%3}, {%4,%5,%6,%7}, {%8,%9}, {%0,%1,%2,%3};"
        : "+f"(d[0]), "+f"(d[1]), "+f"(d[2]), "+f"(d[3])
        : "r"(a[0]), "r"(a[1]), "r"(a[2]), "r"(a[3]), "r"(b0), "r"(b1));
}

__device__ __forceinline__ void vel_to_R(float vx, float vy, float vz, float* R) {
    float rho = sqrtf(vx * vx + vy * vy + vz * vz);
    float theta = atan2f(vy, vx);
    if (theta < 0.0f) theta += 2.0f * PI_F;
    float c = vz / (rho + EPS_F);
    c = fminf(fmaxf(c, -1.0f), 1.0f);
    float phi = acosf(c);
    float st, ct, sp, cp;
    sincosf(theta, &st, &ct);
    sincosf(phi, &sp, &cp);
    R[0] = cp * ct; R[1] = -st;  R[2] = sp * ct;
    R[3] = cp * st; R[4] = ct;   R[5] = sp * st;
    R[6] = -sp;     R[7] = 0.0f; R[8] = cp;
}

// ---------------------------------------------------------------------------
// Kernel 1: per-node rotation matrix + canonical velocity
// ---------------------------------------------------------------------------
__global__ void node_pre_kernel(const float* __restrict__ inp) {
    int idx = blockIdx.x * 128 + threadIdx.x;
    if (idx >= NODES) return;
    const float* v = inp + (size_t)idx * 6 + 3;
    float vx = v[0], vy = v[1], vz = v[2];
    float R[9];
    vel_to_R(vx, vy, vz, R);
#pragma unroll
    for (int i = 0; i < 9; i++) g_R[idx * 9 + i] = R[i];
    g_cv[idx * 3 + 0] = R[0] * vx + R[3] * vy + R[6] * vz;
    g_cv[idx * 3 + 1] = R[1] * vx + R[4] * vy + R[7] * vz;
    g_cv[idx * 3 + 2] = R[2] * vx + R[5] * vy + R[8] * vz;
}

// ---------------------------------------------------------------------------
// Kernel 2: edge aggregation via mma.sync f16.
// Phase 1: ALL 10 nodes' edge features built cooperatively (990 edges over
// 128 threads) into smem. ONE __syncthreads. Phase 2: sync-free sweep —
// each warp does 10 nodes x 13 n-tiles x 2 MMAs with silu epilogue; ILP
// flows across tiles and node boundaries.
// ---------------------------------------------------------------------------
#define EBLOCKS 1280
#define ENODES_PER_BLK 10
#define FSTRIDE 9             // u32 words per edge row (8 f16x2 + 1 pad)
#define NODE_FEAT (104 * FSTRIDE)

__global__ __launch_bounds__(128) void edge_hmma_kernel(
    const float* __restrict__ inp,
    const float* __restrict__ W1,
    const float* __restrict__ b1)
{
    __shared__ uint32_t feat[ENODES_PER_BLK * NODE_FEAT];   // 37,440 B

    int t = threadIdx.x;
    int w = t >> 5;
    int lane = t & 31;
    int g = lane >> 2;        // 0..7
    int t4 = lane & 3;        // 0..3
    int node0 = blockIdx.x * ENODES_PER_BLK;

    // zero feature array (covers k-pad word and edge rows 99..103)
    for (int i = t; i < ENODES_PER_BLK * NODE_FEAT; i += 128) feat[i] = 0u;

    // ---- A fragments: 0.5*W1^T in single fp16 (rows=channels, k pad 0)
    uint32_t Ah[2][4];
#pragma unroll
    for (int mt = 0; mt < 2; mt++) {
        int r0 = w * 32 + mt * 16 + g;
        int r1 = r0 + 8;
        int c0 = 2 * t4;
        int c2 = c0 + 8;
        float v00 = 0.5f * W1[c0 * HH + r0];
        float v01 = 0.5f * W1[(c0 + 1) * HH + r0];
        float v10 = 0.5f * W1[c0 * HH + r1];
        float v11 = 0.5f * W1[(c0 + 1) * HH + r1];
        float v02 = (c2     < 12) ? 0.5f * W1[c2 * HH + r0]       : 0.0f;
        float v03 = (c2 + 1 < 12) ? 0.5f * W1[(c2 + 1) * HH + r0] : 0.0f;
        float v12 = (c2     < 12) ? 0.5f * W1[c2 * HH + r1]       : 0.0f;
        float v13 = (c2 + 1 < 12) ? 0.5f * W1[(c2 + 1) * HH + r1] : 0.0f;
        Ah[mt][0] = f16x2_pack(v00, v01);
        Ah[mt][1] = f16x2_pack(v10, v11);
        Ah[mt][2] = f16x2_pack(v02, v03);
        Ah[mt][3] = f16x2_pack(v12, v13);
    }

    // base-term constants for the 4 owned channel rows (mt-major order)
    float b0h[4], w15[4], w16[4], w17[4];
#pragma unroll
    for (int i = 0; i < 4; i++) {
        int ch = w * 32 + (i >> 1) * 16 + (i & 1) * 8 + g;
        b0h[i] = 0.5f * b1[ch];
        w15[i] = 0.5f * W1[15 * HH + ch];
        w16[i] = 0.5f * W1[16 * HH + ch];
        w17[i] = 0.5f * W1[17 * HH + ch];
    }
    // packed mask for the peeled tile (edges 96..103, keep <99)
    u64 mask2 = pack2((96 + 2 * t4 < 99) ? 1.0f : 0.0f,
                      (97 + 2 * t4 < 99) ? 1.0f : 0.0f);
    __syncthreads();   // zeroing complete before builds write

    // ---- Phase 1: build ALL edges of the block's 10 nodes ----
    for (int idx = t; idx < ENODES_PER_BLK * (NN - 1); idx += 128) {
        int nl = idx / (NN - 1);
        int e = idx - nl * (NN - 1);
        int node = node0 + nl;
        int r_local = node % NN;
        int s = e + (e >= r_local ? 1 : 0);
        int node_s = node - r_local + s;
        const float* xj = inp + (size_t)node_s * 6;
        const float* xi = inp + (size_t)node * 6;
        float Rr[9], Rs[9];
#pragma unroll
        for (int i = 0; i < 9; i++) { Rr[i] = g_R[node * 9 + i]; Rs[i] = g_R[node_s * 9 + i]; }

        float rel0 = xj[0] - xi[0], rel1 = xj[1] - xi[1], rel2 = xj[2] - xi[2];
        float rr0 = Rr[0] * rel0 + Rr[3] * rel1 + Rr[6] * rel2;
        float rr1 = Rr[1] * rel0 + Rr[4] * rel1 + Rr[7] * rel2;
        float rr2 = Rr[2] * rel0 + Rr[5] * rel1 + Rr[8] * rel2;
        float ro00 = Rr[0] * Rs[0] + Rr[3] * Rs[3] + Rr[6] * Rs[6];
        float ro10 = Rr[1] * Rs[0] + Rr[4] * Rs[3] + Rr[7] * Rs[6];
        float ro20 = Rr[2] * Rs[0] + Rr[5] * Rs[3] + Rr[8] * Rs[6];
        float ro21 = Rr[2] * Rs[1] + Rr[5] * Rs[4] + Rr[8] * Rs[7];
        float ro22 = Rr[2] * Rs[2] + Rr[5] * Rs[5] + Rr[8] * Rs[8];

        float f[12];
        f[0] = rr0; f[1] = rr1; f[2] = rr2;
        f[3] = atan2f(ro10, ro00) * (1.0f / PI_F);
        float sa = fminf(fmaxf(-ro20, -1.0f), 1.0f);
        f[4] = asinf(sa) * (1.0f / PI_F);
        f[5] = atan2f(ro21, ro22) * (1.0f / PI_F);
        f[6] = sqrtf(rel0 * rel0 + rel1 * rel1 + rel2 * rel2);
        f[7] = atan2f(rr1, rr0);
        float rho_e = sqrtf(rr0 * rr0 + rr1 * rr1 + rr2 * rr2);
        float cc = rr2 / (rho_e + EPS_F);
        cc = fminf(fmaxf(cc, -1.0f), 1.0f);
        f[8] = acosf(cc);
        float vj0 = xj[3], vj1 = xj[4], vj2 = xj[5];
        f[9]  = Rr[0] * vj0 + Rr[3] * vj1 + Rr[6] * vj2;
        f[10] = Rr[1] * vj0 + Rr[4] * vj1 + Rr[7] * vj2;
        f[11] = Rr[2] * vj0 + Rr[5] * vj1 + Rr[8] * vj2;

        int rb = nl * NODE_FEAT + e * FSTRIDE;
#pragma unroll
        for (int k2 = 0; k2 < 6; k2++)
            feat[rb + k2] = f16x2_pack(f[2 * k2], f[2 * k2 + 1]);
    }
    __syncthreads();   // the only build->compute sync

    // ---- Phase 2: sync-free sweep over 10 nodes ----
#pragma unroll 1
    for (int ni = 0; ni < ENODES_PER_BLK; ni++) {
        int node = node0 + ni;
        const uint32_t* nf = feat + ni * NODE_FEAT;

        float cv0 = g_cv[node * 3], cv1 = g_cv[node * 3 + 1], cv2 = g_cv[node * 3 + 2];
        u64 base2[4];
#pragma unroll
        for (int i = 0; i < 4; i++) {
            float b = fmaf(cv2, w17[i], fmaf(cv1, w16[i], fmaf(cv0, w15[i], b0h[i])));
            base2[i] = pack2(b, b);
        }

        u64 accM[4] = {0, 0, 0, 0}, accT[4] = {0, 0, 0, 0};

#pragma unroll 2
        for (int nt = 0; nt < 12; nt++) {
            const uint32_t* fp = nf + (nt * 8 + g) * FSTRIDE;
            uint32_t b0 = fp[t4], b1v = fp[4 + t4];

            float d0[4] = {0.f, 0.f, 0.f, 0.f};
            float d1[4] = {0.f, 0.f, 0.f, 0.f};
            mma_f16(d0, Ah[0], b0, b1v);
            mma_f16(d1, Ah[1], b0, b1v);

            u64 m0 = add2(packu(__float_as_uint(d0[0]), __float_as_uint(d0[1])), base2[0]);
            u64 m1 = add2(packu(__float_as_uint(d0[2]), __float_as_uint(d0[3])), base2[1]);
            u64 m2 = add2(packu(__float_as_uint(d1[0]), __float_as_uint(d1[1])), base2[2]);
            u64 m3 = add2(packu(__float_as_uint(d1[2]), __float_as_uint(d1[3])), base2[3]);
            float a, b;
            unpack2(m0, a, b); u64 t0 = pack2(tanh_fast(a), tanh_fast(b));
            unpack2(m1, a, b); u64 t1 = pack2(tanh_fast(a), tanh_fast(b));
            unpack2(m2, a, b); u64 t2 = pack2(tanh_fast(a), tanh_fast(b));
            unpack2(m3, a, b); u64 t3 = pack2(tanh_fast(a), tanh_fast(b));
            accM[0] = add2(accM[0], m0); accT[0] = fma2(m0, t0, accT[0]);
            accM[1] = add2(accM[1], m1); accT[1] = fma2(m1, t1, accT[1]);
            accM[2] = add2(accM[2], m2); accT[2] = fma2(m2, t2, accT[2]);
            accM[3] = add2(accM[3], m3); accT[3] = fma2(m3, t3, accT[3]);
        }
        // ---- peeled tile 12 (edges 96..98 real) ----
        {
            const uint32_t* fp = nf + (12 * 8 + g) * FSTRIDE;
            uint32_t b0 = fp[t4], b1v = fp[4 + t4];
            float d0[4] = {0.f, 0.f, 0.f, 0.f};
            float d1[4] = {0.f, 0.f, 0.f, 0.f};
            mma_f16(d0, Ah[0], b0, b1v);
            mma_f16(d1, Ah[1], b0, b1v);
            u64 m0 = mul2(add2(packu(__float_as_uint(d0[0]), __float_as_uint(d0[1])), base2[0]), mask2);
            u64 m1 = mul2(add2(packu(__float_as_uint(d0[2]), __float_as_uint(d0[3])), base2[1]), mask2);
            u64 m2 = mul2(add2(packu(__float_as_uint(d1[0]), __float_as_uint(d1[1])), base2[2]), mask2);
            u64 m3 = mul2(add2(packu(__float_as_uint(d1[2]), __float_as_uint(d1[3])), base2[3]), mask2);
            float a, b;
            unpack2(m0, a, b); u64 t0 = pack2(tanh_fast(a), tanh_fast(b));
            unpack2(m1, a, b); u64 t1 = pack2(tanh_fast(a), tanh_fast(b));
            unpack2(m2, a, b); u64 t2 = pack2(tanh_fast(a), tanh_fast(b));
            unpack2(m3, a, b); u64 t3 = pack2(tanh_fast(a), tanh_fast(b));
            accM[0] = add2(accM[0], m0); accT[0] = fma2(m0, t0, accT[0]);
            accM[1] = add2(accM[1], m1); accT[1] = fma2(m1, t1, accT[1]);
            accM[2] = add2(accM[2], m2); accT[2] = fma2(m2, t2, accT[2]);
            accM[3] = add2(accM[3], m3); accT[3] = fma2(m3, t3, accT[3]);
        }

        // ---- reduce across the 4 lanes of each row-group, store ----
        float acc[4];
#pragma unroll
        for (int i = 0; i < 4; i++) {
            float ml, mh, tl, th;
            unpack2(accM[i], ml, mh);
            unpack2(accT[i], tl, th);
            acc[i] = ml + mh + tl + th;
            acc[i] += __shfl_xor_sync(0xffffffffu, acc[i], 1);
            acc[i] += __shfl_xor_sync(0xffffffffu, acc[i], 2);
        }
        if (t4 == 0) {
            float* hp = &g_hacc[(size_t)node * HH + w * 32 + g];
            hp[0]  = acc[0];
            hp[8]  = acc[1];
            hp[16] = acc[2];
            hp[24] = acc[3];
        }
    }
}

// ---------------------------------------------------------------------------
// Kernel 3: register-tiled GEMM MLP (unchanged, proven)
// ---------------------------------------------------------------------------
#define MLP_BLOCKS 134
#define MLP_THREADS 384
#define NT 96
#define OFF_WT  0
#define OFF_A   16384
#define OFF_B   28672
#define OFF_W5T 40960
#define OFF_WR  41728
#define OFF_B2R 42112
#define OFF_B3  42240
#define OFF_B4  42368
#define OFF_B5  42496
#define SMEM_FL 42504

__device__ __forceinline__ int a_fidx(int n, int k) {
    return (n * 64 + ((k >> 1) ^ ((n >> 3) & 3))) * 2 + (k & 1);
}

template <int MODE>
__device__ __forceinline__ void gemm_layer(
    const u64* __restrict__ Ain, float* __restrict__ Bout,
    const u64* __restrict__ Wt, const float* __restrict__ bias,
    int n0, const float* __restrict__ wrS)
{
    int t = threadIdx.x;
    int warp = t >> 5, lane = t & 31;
    int wr = warp >> 2, wc = warp & 3;
    int ng = lane >> 3, cg = lane & 7;
    int nb = wr * 32 + ng * 8;
    int cb = wc * 32 + cg * 4;
    int swzx = (nb >> 3) & 3;
    int swzw = cg;

    const u64* Ap = Ain + nb * 64;
    const u64* Wp = Wt + cb * 64;

    u64 acc[8][4];
#pragma unroll
    for (int i = 0; i < 8; i++)
#pragma unroll
        for (int j = 0; j < 4; j++) acc[i][j] = 0ull;

#pragma unroll 4
    for (int kp = 0; kp < 64; kp++) {
        int ox = kp ^ swzx;
        int ow = kp ^ swzw;
        u64 xr[8], wv[4];
#pragma unroll
        for (int i = 0; i < 8; i++) xr[i] = Ap[i * 64 + ox];
#pragma unroll
        for (int j = 0; j < 4; j++) wv[j] = Wp[j * 64 + ow];
#pragma unroll
        for (int i = 0; i < 8; i++)
#pragma unroll
            for (int j = 0; j < 4; j++) acc[i][j] = fma2(xr[i], wv[j], acc[i][j]);
    }

#pragma unroll
    for (int i = 0; i < 8; i++) {
        int n = nb + i;
        int sw = (n >> 3) & 3;
        float cvx = 0.f, cvy = 0.f, cvz = 0.f;
        if (MODE == 0) {
            int gn = n0 + n;
            cvx = g_cv[gn * 3 + 0]; cvy = g_cv[gn * 3 + 1]; cvz = g_cv[gn * 3 + 2];
        }
#pragma unroll
        for (int j = 0; j < 4; j++) {
            int c = cb + j;
            float lo, hi;
            unpack2(acc[i][j], lo, hi);
            float s = lo + hi + bias[c];
            if (MODE == 0) s += cvx * wrS[c] + cvy * wrS[128 + c] + cvz * wrS[256 + c];
            else s = fmaxf(s, 0.0f);
            Bout[(n * 64 + ((c >> 1) ^ sw)) * 2 + (c & 1)] = s;
        }
    }
}

__global__ __launch_bounds__(MLP_THREADS, 1) void node_mlp_kernel(
    const float* __restrict__ inp,
    const float* __restrict__ W2, const float* __restrict__ b2,
    const float* __restrict__ Wr, const float* __restrict__ br,
    const float* __restrict__ W3, const float* __restrict__ b3,
    const float* __restrict__ W4, const float* __restrict__ b4,
    const float* __restrict__ W5, const float* __restrict__ b5,
    float* __restrict__ out)
{
    extern __shared__ float sm[];
    int t = threadIdx.x;
    int n0 = blockIdx.x * NT;
    const float inv99 = 1.0f / 99.0f;

    for (int idx = t; idx < NT * 128; idx += MLP_THREADS) {
        int n = idx >> 7, k = idx & 127;
        sm[OFF_A + a_fidx(n, k)] = g_hacc[(size_t)(n0 + n) * 128 + k] * inv99;
    }
    for (int idx = t; idx < 768; idx += MLP_THREADS) {
        int k = idx / 6, j = idx % 6;
        sm[OFF_W5T + j * 128 + k] = W5[idx];
    }
    for (int idx = t; idx < 384; idx += MLP_THREADS) sm[OFF_WR + idx] = Wr[384 + idx];
    if (t < 128) {
        sm[OFF_B2R + t] = b2[t] + br[t];
        sm[OFF_B3 + t] = b3[t];
        sm[OFF_B4 + t] = b4[t];
    }
    if (t < 6) sm[OFF_B5 + t] = b5[t];

    u64* A64 = (u64*)(sm + OFF_A);
    u64* B64 = (u64*)(sm + OFF_B);
    u64* Wt64 = (u64*)(sm + OFF_WT);

    for (int idx = t; idx < 16384; idx += MLP_THREADS) {
        int k = idx >> 7, c = idx & 127;
        sm[OFF_WT + (c * 64 + ((k >> 1) ^ ((c >> 2) & 7))) * 2 + (k & 1)] = W2[idx];
    }
    __syncthreads();
    gemm_layer<0>(A64, sm + OFF_B, Wt64, sm + OFF_B2R, n0, sm + OFF_WR);
    __syncthreads();

    for (int idx = t; idx < 16384; idx += MLP_THREADS) {
        int k = idx >> 7, c = idx & 127;
        sm[OFF_WT + (c * 64 + ((k >> 1) ^ ((c >> 2) & 7))) * 2 + (k & 1)] = W3[idx];
    }
    __syncthreads();
    gemm_layer<1>(B64, sm + OFF_A, Wt64, sm + OFF_B3, n0, nullptr);
    __syncthreads();

    for (int idx = t; idx < 16384; idx += MLP_THREADS) {
        int k = idx >> 7, c = idx & 127;
        sm[OFF_WT + (c * 64 + ((k >> 1) ^ ((c >> 2) & 7))) * 2 + (k & 1)] = W4[idx];
    }
    __syncthreads();
    gemm_layer<1>(A64, sm + OFF_B, Wt64, sm + OFF_B4, n0, nullptr);
    __syncthreads();

    if (t < NT) {
        int gnode = n0 + t;
        if (gnode < NODES) {
            int sw = (t >> 3) & 3;
            const u64* Pp = B64 + t * 64;
            u64 sj2[6];
#pragma unroll
            for (int j = 0; j < 6; j++) sj2[j] = 0ull;
#pragma unroll 8
            for (int kp = 0; kp < 64; kp++) {
                u64 x2 = Pp[kp ^ sw];
#pragma unroll
                for (int j = 0; j < 6; j++) {
                    u64 w2 = *(const u64*)&sm[OFF_W5T + j * 128 + 2 * kp];
                    sj2[j] = fma2(x2, w2, sj2[j]);
                }
            }
            float pred[6];
#pragma unroll
            for (int j = 0; j < 6; j++) {
                float lo, hi;
                unpack2(sj2[j], lo, hi);
                pred[j] = lo + hi + sm[OFF_B5 + j];
            }
            const float* R = g_R + (size_t)gnode * 9;
            float Rl[9];
#pragma unroll
            for (int i = 0; i < 9; i++) Rl[i] = R[i];
            const float* xin = inp + (size_t)gnode * 6;
            float* xout = out + (size_t)gnode * 6;
#pragma unroll
            for (int j = 0; j < 6; j++) {
                int i = j % 3, off = (j / 3) * 3;
                float gl = Rl[i * 3 + 0] * pred[off + 0]
                         + Rl[i * 3 + 1] * pred[off + 1]
                         + Rl[i * 3 + 2] * pred[off + 2];
                xout[j] = xin[j] + gl;
            }
        }
    }
}

// ---------------------------------------------------------------------------
extern "C" void kernel_launch(void* const* d_in, const int* in_sizes, int n_in,
                              void* d_out, int out_size)
{
    const float* inp = (const float*)d_in[0];
    const float* W1  = (const float*)d_in[1];
    const float* b1  = (const float*)d_in[2];
    const float* W2  = (const float*)d_in[3];
    const float* b2  = (const float*)d_in[4];
    const float* Wr  = (const float*)d_in[5];
    const float* br  = (const float*)d_in[6];
    const float* W3  = (const float*)d_in[7];
    const float* b3  = (const float*)d_in[8];
    const float* W4  = (const float*)d_in[9];
    const float* b4  = (const float*)d_in[10];
    const float* W5  = (const float*)d_in[11];
    const float* b5  = (const float*)d_in[12];
    float* out = (float*)d_out;

    const int SMEM3 = SMEM_FL * 4;
    cudaFuncSetAttribute(node_mlp_kernel,
                         cudaFuncAttributeMaxDynamicSharedMemorySize, SMEM3);

    node_pre_kernel<<<NODES / 128, 128>>>(inp);
    edge_hmma_kernel<<<EBLOCKS, 128>>>(inp, W1, b1);
    node_mlp_kernel<<<MLP_BLOCKS, MLP_THREADS, SMEM3>>>(inp, W2, b2, Wr, br,
                                                        W3, b3, W4, b4, W5, b5, out);
}

// round 16
// speedup vs baseline: 1.5007x; 1.5007x over previous
#include <cuda_runtime.h>
#include <cuda_fp16.h>
#include <math.h>
#include <stdint.h>

#define BB 128
#define NN 100
#define HH 128
#define NODES (BB*NN)          // 12800
#define NODES_PAD 12864
#define PI_F 3.14159265358979323846f
#define EPS_F 1e-7f

__device__ float g_R[NODES_PAD * 9];
__device__ float g_cv[NODES_PAD * 3];
__device__ float g_hacc[NODES_PAD * HH];

typedef unsigned long long u64;

// ---- packed f32x2 helpers -------------------------------------------------
__device__ __forceinline__ u64 fma2(u64 a, u64 b, u64 c) {
    u64 d;
    asm("fma.rn.f32x2 %0, %1, %2, %3;" : "=l"(d) : "l"(a), "l"(b), "l"(c));
    return d;
}
__device__ __forceinline__ u64 add2(u64 a, u64 b) {
    u64 d; asm("add.rn.f32x2 %0, %1, %2;" : "=l"(d) : "l"(a), "l"(b)); return d;
}
__device__ __forceinline__ u64 mul2(u64 a, u64 b) {
    u64 d; asm("mul.rn.f32x2 %0, %1, %2;" : "=l"(d) : "l"(a), "l"(b)); return d;
}
__device__ __forceinline__ u64 pack2(float lo, float hi) {
    u64 d; asm("mov.b64 %0, {%1, %2};" : "=l"(d) : "f"(lo), "f"(hi)); return d;
}
__device__ __forceinline__ u64 packu(uint32_t a, uint32_t b) {
    u64 d; asm("mov.b64 %0, {%1, %2};" : "=l"(d) : "r"(a), "r"(b)); return d;
}
__device__ __forceinline__ void unpack2(u64 v, float& lo, float& hi) {
    asm("mov.b64 {%0, %1}, %2;" : "=f"(lo), "=f"(hi) : "l"(v));
}
__device__ __forceinline__ float tanh_fast(float x) {
    float r; asm("tanh.approx.f32 %0, %1;" : "=f"(r) : "f"(x)); return r;
}
// pack two f32 -> f16x2 (lo in low half)
__device__ __forceinline__ uint32_t f16x2_pack(float lo, float hi) {
    uint32_t r;
    asm("cvt.rn.f16x2.f32 %0, %1, %2;" : "=r"(r) : "f"(hi), "f"(lo));
    return r;
}

// mma.sync m16n8k16 row.col f16 -> f32 accumulate
__device__ __forceinline__ void mma_f16(float* d, const uint32_t* a,
                                        uint32_t b0, uint32_t b1) {
    asm volatile(
        "mma.sync.aligned.m16n8k16.row.col.f32.f16.f16.f32 "
        "{%0,%1,%2,%3}, {%4,%5,%6,%7}, {%8,%9}, {%0,%1,%2,%3};"
        : "+f"(d[0]), "+f"(d[1]), "+f"(d[2]), "+f"(d[3])
        : "r"(a[0]), "r"(a[1]), "r"(a[2]), "r"(a[3]), "r"(b0), "r"(b1));
}

__device__ __forceinline__ void vel_to_R(float vx, float vy, float vz, float* R) {
    float rho = sqrtf(vx * vx + vy * vy + vz * vz);
    float theta = atan2f(vy, vx);
    if (theta < 0.0f) theta += 2.0f * PI_F;
    float c = vz / (rho + EPS_F);
    c = fminf(fmaxf(c, -1.0f), 1.0f);
    float phi = acosf(c);
    float st, ct, sp, cp;
    sincosf(theta, &st, &ct);
    sincosf(phi, &sp, &cp);
    R[0] = cp * ct; R[1] = -st;  R[2] = sp * ct;
    R[3] = cp * st; R[4] = ct;   R[5] = sp * st;
    R[6] = -sp;     R[7] = 0.0f; R[8] = cp;
}

// ---------------------------------------------------------------------------
// Kernel 1: per-node rotation matrix + canonical velocity
// ---------------------------------------------------------------------------
__global__ void node_pre_kernel(const float* __restrict__ inp) {
    int idx = blockIdx.x * 128 + threadIdx.x;
    if (idx >= NODES) return;
    const float* v = inp + (size_t)idx * 6 + 3;
    float vx = v[0], vy = v[1], vz = v[2];
    float R[9];
    vel_to_R(vx, vy, vz, R);
#pragma unroll
    for (int i = 0; i < 9; i++) g_R[idx * 9 + i] = R[i];
    g_cv[idx * 3 + 0] = R[0] * vx + R[3] * vy + R[6] * vz;
    g_cv[idx * 3 + 1] = R[1] * vx + R[4] * vy + R[7] * vz;
    g_cv[idx * 3 + 2] = R[2] * vx + R[5] * vy + R[8] * vz;
}

// ---------------------------------------------------------------------------
// Kernel 2: edge aggregation via mma.sync f16 — R13 structure with TWO nodes
// interleaved per iteration (independent MMA + epilogue chains for ILP) and
// merged silu accumulators. smem 2 x 3.7KB keeps R13-level occupancy.
// ---------------------------------------------------------------------------
#define EBLOCKS 1280
#define ENODES_PER_BLK 10
#define FSTRIDE 9             // u32 words per edge row (8 f16x2 + 1 pad)
#define NODE_FEAT (104 * FSTRIDE)

__device__ __forceinline__ void build_edge(const float* __restrict__ inp,
                                           int node, int e, uint32_t* dst) {
    int r_local = node % NN;
    int s = e + (e >= r_local ? 1 : 0);
    int node_s = node - r_local + s;
    const float* xj = inp + (size_t)node_s * 6;
    const float* xi = inp + (size_t)node * 6;
    float Rr[9], Rs[9];
#pragma unroll
    for (int i = 0; i < 9; i++) { Rr[i] = g_R[node * 9 + i]; Rs[i] = g_R[node_s * 9 + i]; }

    float rel0 = xj[0] - xi[0], rel1 = xj[1] - xi[1], rel2 = xj[2] - xi[2];
    float rr0 = Rr[0] * rel0 + Rr[3] * rel1 + Rr[6] * rel2;
    float rr1 = Rr[1] * rel0 + Rr[4] * rel1 + Rr[7] * rel2;
    float rr2 = Rr[2] * rel0 + Rr[5] * rel1 + Rr[8] * rel2;
    float ro00 = Rr[0] * Rs[0] + Rr[3] * Rs[3] + Rr[6] * Rs[6];
    float ro10 = Rr[1] * Rs[0] + Rr[4] * Rs[3] + Rr[7] * Rs[6];
    float ro20 = Rr[2] * Rs[0] + Rr[5] * Rs[3] + Rr[8] * Rs[6];
    float ro21 = Rr[2] * Rs[1] + Rr[5] * Rs[4] + Rr[8] * Rs[7];
    float ro22 = Rr[2] * Rs[2] + Rr[5] * Rs[5] + Rr[8] * Rs[8];

    float f[12];
    f[0] = rr0; f[1] = rr1; f[2] = rr2;
    f[3] = atan2f(ro10, ro00) * (1.0f / PI_F);
    float sa = fminf(fmaxf(-ro20, -1.0f), 1.0f);
    f[4] = asinf(sa) * (1.0f / PI_F);
    f[5] = atan2f(ro21, ro22) * (1.0f / PI_F);
    f[6] = sqrtf(rel0 * rel0 + rel1 * rel1 + rel2 * rel2);
    f[7] = atan2f(rr1, rr0);
    float rho_e = sqrtf(rr0 * rr0 + rr1 * rr1 + rr2 * rr2);
    float cc = rr2 / (rho_e + EPS_F);
    cc = fminf(fmaxf(cc, -1.0f), 1.0f);
    f[8] = acosf(cc);
    float vj0 = xj[3], vj1 = xj[4], vj2 = xj[5];
    f[9]  = Rr[0] * vj0 + Rr[3] * vj1 + Rr[6] * vj2;
    f[10] = Rr[1] * vj0 + Rr[4] * vj1 + Rr[7] * vj2;
    f[11] = Rr[2] * vj0 + Rr[5] * vj1 + Rr[8] * vj2;

    uint32_t* row = dst + e * FSTRIDE;
#pragma unroll
    for (int k2 = 0; k2 < 6; k2++)
        row[k2] = f16x2_pack(f[2 * k2], f[2 * k2 + 1]);
}

__global__ __launch_bounds__(128) void edge_hmma_kernel(
    const float* __restrict__ inp,
    const float* __restrict__ W1,
    const float* __restrict__ b1)
{
    __shared__ uint32_t feat[2][NODE_FEAT];   // 7,488 B

    int t = threadIdx.x;
    int w = t >> 5;
    int lane = t & 31;
    int g = lane >> 2;        // 0..7
    int t4 = lane & 3;        // 0..3
    int node0 = blockIdx.x * ENODES_PER_BLK;

    // zero both buffers once (covers k-pad word and edge rows 99..103)
    for (int i = t; i < 2 * NODE_FEAT; i += 128) feat[0][i] = 0u;

    // ---- A fragments: 0.5*W1^T in single fp16 (rows=channels, k pad 0)
    uint32_t Ah[2][4];
#pragma unroll
    for (int mt = 0; mt < 2; mt++) {
        int r0 = w * 32 + mt * 16 + g;
        int r1 = r0 + 8;
        int c0 = 2 * t4;
        int c2 = c0 + 8;
        float v00 = 0.5f * W1[c0 * HH + r0];
        float v01 = 0.5f * W1[(c0 + 1) * HH + r0];
        float v10 = 0.5f * W1[c0 * HH + r1];
        float v11 = 0.5f * W1[(c0 + 1) * HH + r1];
        float v02 = (c2     < 12) ? 0.5f * W1[c2 * HH + r0]       : 0.0f;
        float v03 = (c2 + 1 < 12) ? 0.5f * W1[(c2 + 1) * HH + r0] : 0.0f;
        float v12 = (c2     < 12) ? 0.5f * W1[c2 * HH + r1]       : 0.0f;
        float v13 = (c2 + 1 < 12) ? 0.5f * W1[(c2 + 1) * HH + r1] : 0.0f;
        Ah[mt][0] = f16x2_pack(v00, v01);
        Ah[mt][1] = f16x2_pack(v10, v11);
        Ah[mt][2] = f16x2_pack(v02, v03);
        Ah[mt][3] = f16x2_pack(v12, v13);
    }

    // base-term constants for the 4 owned channel rows (mt-major order)
    float b0h[4], w15[4], w16[4], w17[4];
#pragma unroll
    for (int i = 0; i < 4; i++) {
        int ch = w * 32 + (i >> 1) * 16 + (i & 1) * 8 + g;
        b0h[i] = 0.5f * b1[ch];
        w15[i] = 0.5f * W1[15 * HH + ch];
        w16[i] = 0.5f * W1[16 * HH + ch];
        w17[i] = 0.5f * W1[17 * HH + ch];
    }
    // packed mask for the peeled tile (edges 96..103, keep <99)
    u64 mask2 = pack2((96 + 2 * t4 < 99) ? 1.0f : 0.0f,
                      (97 + 2 * t4 < 99) ? 1.0f : 0.0f);
    __syncthreads();   // zeroing complete before builds write

#pragma unroll 1
    for (int ni = 0; ni < ENODES_PER_BLK; ni += 2) {
        int nA = node0 + ni;
        int nB = nA + 1;

        // ---- build both nodes' edge t (independent -> ILP) ----
        if (t < NN - 1) {
            build_edge(inp, nA, t, feat[0]);
            build_edge(inp, nB, t, feat[1]);
        }
        __syncthreads();

        // ---- per-node bases (packed) ----
        u64 baseA[4], baseB[4];
        {
            float a0 = g_cv[nA * 3], a1 = g_cv[nA * 3 + 1], a2 = g_cv[nA * 3 + 2];
            float c0 = g_cv[nB * 3], c1 = g_cv[nB * 3 + 1], c2 = g_cv[nB * 3 + 2];
#pragma unroll
            for (int i = 0; i < 4; i++) {
                float bA = fmaf(a2, w17[i], fmaf(a1, w16[i], fmaf(a0, w15[i], b0h[i])));
                float bB = fmaf(c2, w17[i], fmaf(c1, w16[i], fmaf(c0, w15[i], b0h[i])));
                baseA[i] = pack2(bA, bA);
                baseB[i] = pack2(bB, bB);
            }
        }

        u64 accA[4] = {0, 0, 0, 0}, accB[4] = {0, 0, 0, 0};

#pragma unroll 1
        for (int nt = 0; nt < 12; nt++) {
            const uint32_t* fA = &feat[0][(nt * 8 + g) * FSTRIDE];
            const uint32_t* fB = &feat[1][(nt * 8 + g) * FSTRIDE];
            uint32_t a0 = fA[t4], a1 = fA[4 + t4];
            uint32_t b0 = fB[t4], b1v = fB[4 + t4];

            float dA0[4] = {0.f, 0.f, 0.f, 0.f};
            float dA1[4] = {0.f, 0.f, 0.f, 0.f};
            float dB0[4] = {0.f, 0.f, 0.f, 0.f};
            float dB1[4] = {0.f, 0.f, 0.f, 0.f};
            mma_f16(dA0, Ah[0], a0, a1);
            mma_f16(dA1, Ah[1], a0, a1);
            mma_f16(dB0, Ah[0], b0, b1v);
            mma_f16(dB1, Ah[1], b0, b1v);

            u64 mA0 = add2(packu(__float_as_uint(dA0[0]), __float_as_uint(dA0[1])), baseA[0]);
            u64 mA1 = add2(packu(__float_as_uint(dA0[2]), __float_as_uint(dA0[3])), baseA[1]);
            u64 mA2 = add2(packu(__float_as_uint(dA1[0]), __float_as_uint(dA1[1])), baseA[2]);
            u64 mA3 = add2(packu(__float_as_uint(dA1[2]), __float_as_uint(dA1[3])), baseA[3]);
            u64 mB0 = add2(packu(__float_as_uint(dB0[0]), __float_as_uint(dB0[1])), baseB[0]);
            u64 mB1 = add2(packu(__float_as_uint(dB0[2]), __float_as_uint(dB0[3])), baseB[1]);
            u64 mB2 = add2(packu(__float_as_uint(dB1[0]), __float_as_uint(dB1[1])), baseB[2]);
            u64 mB3 = add2(packu(__float_as_uint(dB1[2]), __float_as_uint(dB1[3])), baseB[3]);
            float x, y;
            unpack2(mA0, x, y); u64 tA0 = pack2(tanh_fast(x), tanh_fast(y));
            unpack2(mA1, x, y); u64 tA1 = pack2(tanh_fast(x), tanh_fast(y));
            unpack2(mA2, x, y); u64 tA2 = pack2(tanh_fast(x), tanh_fast(y));
            unpack2(mA3, x, y); u64 tA3 = pack2(tanh_fast(x), tanh_fast(y));
            unpack2(mB0, x, y); u64 tB0 = pack2(tanh_fast(x), tanh_fast(y));
            unpack2(mB1, x, y); u64 tB1 = pack2(tanh_fast(x), tanh_fast(y));
            unpack2(mB2, x, y); u64 tB2 = pack2(tanh_fast(x), tanh_fast(y));
            unpack2(mB3, x, y); u64 tB3 = pack2(tanh_fast(x), tanh_fast(y));
            accA[0] = fma2(mA0, tA0, add2(accA[0], mA0));
            accA[1] = fma2(mA1, tA1, add2(accA[1], mA1));
            accA[2] = fma2(mA2, tA2, add2(accA[2], mA2));
            accA[3] = fma2(mA3, tA3, add2(accA[3], mA3));
            accB[0] = fma2(mB0, tB0, add2(accB[0], mB0));
            accB[1] = fma2(mB1, tB1, add2(accB[1], mB1));
            accB[2] = fma2(mB2, tB2, add2(accB[2], mB2));
            accB[3] = fma2(mB3, tB3, add2(accB[3], mB3));
        }
        // ---- peeled tile 12 (edges 96..98 real) ----
        {
            const uint32_t* fA = &feat[0][(12 * 8 + g) * FSTRIDE];
            const uint32_t* fB = &feat[1][(12 * 8 + g) * FSTRIDE];
            uint32_t a0 = fA[t4], a1 = fA[4 + t4];
            uint32_t b0 = fB[t4], b1v = fB[4 + t4];
            float dA0[4] = {0.f, 0.f, 0.f, 0.f};
            float dA1[4] = {0.f, 0.f, 0.f, 0.f};
            float dB0[4] = {0.f, 0.f, 0.f, 0.f};
            float dB1[4] = {0.f, 0.f, 0.f, 0.f};
            mma_f16(dA0, Ah[0], a0, a1);
            mma_f16(dA1, Ah[1], a0, a1);
            mma_f16(dB0, Ah[0], b0, b1v);
            mma_f16(dB1, Ah[1], b0, b1v);
            u64 mA0 = mul2(add2(packu(__float_as_uint(dA0[0]), __float_as_uint(dA0[1])), baseA[0]), mask2);
            u64 mA1 = mul2(add2(packu(__float_as_uint(dA0[2]), __float_as_uint(dA0[3])), baseA[1]), mask2);
            u64 mA2 = mul2(add2(packu(__float_as_uint(dA1[0]), __float_as_uint(dA1[1])), baseA[2]), mask2);
            u64 mA3 = mul2(add2(packu(__float_as_uint(dA1[2]), __float_as_uint(dA1[3])), baseA[3]), mask2);
            u64 mB0 = mul2(add2(packu(__float_as_uint(dB0[0]), __float_as_uint(dB0[1])), baseB[0]), mask2);
            u64 mB1 = mul2(add2(packu(__float_as_uint(dB0[2]), __float_as_uint(dB0[3])), baseB[1]), mask2);
            u64 mB2 = mul2(add2(packu(__float_as_uint(dB1[0]), __float_as_uint(dB1[1])), baseB[2]), mask2);
            u64 mB3 = mul2(add2(packu(__float_as_uint(dB1[2]), __float_as_uint(dB1[3])), baseB[3]), mask2);
            float x, y;
            unpack2(mA0, x, y); u64 tA0 = pack2(tanh_fast(x), tanh_fast(y));
            unpack2(mA1, x, y); u64 tA1 = pack2(tanh_fast(x), tanh_fast(y));
            unpack2(mA2, x, y); u64 tA2 = pack2(tanh_fast(x), tanh_fast(y));
            unpack2(mA3, x, y); u64 tA3 = pack2(tanh_fast(x), tanh_fast(y));
            unpack2(mB0, x, y); u64 tB0 = pack2(tanh_fast(x), tanh_fast(y));
            unpack2(mB1, x, y); u64 tB1 = pack2(tanh_fast(x), tanh_fast(y));
            unpack2(mB2, x, y); u64 tB2 = pack2(tanh_fast(x), tanh_fast(y));
            unpack2(mB3, x, y); u64 tB3 = pack2(tanh_fast(x), tanh_fast(y));
            accA[0] = fma2(mA0, tA0, add2(accA[0], mA0));
            accA[1] = fma2(mA1, tA1, add2(accA[1], mA1));
            accA[2] = fma2(mA2, tA2, add2(accA[2], mA2));
            accA[3] = fma2(mA3, tA3, add2(accA[3], mA3));
            accB[0] = fma2(mB0, tB0, add2(accB[0], mB0));
            accB[1] = fma2(mB1, tB1, add2(accB[1], mB1));
            accB[2] = fma2(mB2, tB2, add2(accB[2], mB2));
            accB[3] = fma2(mB3, tB3, add2(accB[3], mB3));
        }

        // ---- reduce + store both nodes ----
        float rA[4], rB[4];
#pragma unroll
        for (int i = 0; i < 4; i++) {
            float ml, mh;
            unpack2(accA[i], ml, mh);
            rA[i] = ml + mh;
            unpack2(accB[i], ml, mh);
            rB[i] = ml + mh;
            rA[i] += __shfl_xor_sync(0xffffffffu, rA[i], 1);
            rB[i] += __shfl_xor_sync(0xffffffffu, rB[i], 1);
            rA[i] += __shfl_xor_sync(0xffffffffu, rA[i], 2);
            rB[i] += __shfl_xor_sync(0xffffffffu, rB[i], 2);
        }
        if (t4 == 0) {
            float* hA = &g_hacc[(size_t)nA * HH + w * 32 + g];
            float* hB = &g_hacc[(size_t)nB * HH + w * 32 + g];
            hA[0] = rA[0]; hA[8] = rA[1]; hA[16] = rA[2]; hA[24] = rA[3];
            hB[0] = rB[0]; hB[8] = rB[1]; hB[16] = rB[2]; hB[24] = rB[3];
        }
        __syncthreads();   // protect feat before next build
    }
}

// ---------------------------------------------------------------------------
// Kernel 3: register-tiled GEMM MLP (unchanged, proven)
// ---------------------------------------------------------------------------
#define MLP_BLOCKS 134
#define MLP_THREADS 384
#define NT 96
#define OFF_WT  0
#define OFF_A   16384
#define OFF_B   28672
#define OFF_W5T 40960
#define OFF_WR  41728
#define OFF_B2R 42112
#define OFF_B3  42240
#define OFF_B4  42368
#define OFF_B5  42496
#define SMEM_FL 42504

__device__ __forceinline__ int a_fidx(int n, int k) {
    return (n * 64 + ((k >> 1) ^ ((n >> 3) & 3))) * 2 + (k & 1);
}

template <int MODE>
__device__ __forceinline__ void gemm_layer(
    const u64* __restrict__ Ain, float* __restrict__ Bout,
    const u64* __restrict__ Wt, const float* __restrict__ bias,
    int n0, const float* __restrict__ wrS)
{
    int t = threadIdx.x;
    int warp = t >> 5, lane = t & 31;
    int wr = warp >> 2, wc = warp & 3;
    int ng = lane >> 3, cg = lane & 7;
    int nb = wr * 32 + ng * 8;
    int cb = wc * 32 + cg * 4;
    int swzx = (nb >> 3) & 3;
    int swzw = cg;

    const u64* Ap = Ain + nb * 64;
    const u64* Wp = Wt + cb * 64;

    u64 acc[8][4];
#pragma unroll
    for (int i = 0; i < 8; i++)
#pragma unroll
        for (int j = 0; j < 4; j++) acc[i][j] = 0ull;

#pragma unroll 4
    for (int kp = 0; kp < 64; kp++) {
        int ox = kp ^ swzx;
        int ow = kp ^ swzw;
        u64 xr[8], wv[4];
#pragma unroll
        for (int i = 0; i < 8; i++) xr[i] = Ap[i * 64 + ox];
#pragma unroll
        for (int j = 0; j < 4; j++) wv[j] = Wp[j * 64 + ow];
#pragma unroll
        for (int i = 0; i < 8; i++)
#pragma unroll
            for (int j = 0; j < 4; j++) acc[i][j] = fma2(xr[i], wv[j], acc[i][j]);
    }

#pragma unroll
    for (int i = 0; i < 8; i++) {
        int n = nb + i;
        int sw = (n >> 3) & 3;
        float cvx = 0.f, cvy = 0.f, cvz = 0.f;
        if (MODE == 0) {
            int gn = n0 + n;
            cvx = g_cv[gn * 3 + 0]; cvy = g_cv[gn * 3 + 1]; cvz = g_cv[gn * 3 + 2];
        }
#pragma unroll
        for (int j = 0; j < 4; j++) {
            int c = cb + j;
            float lo, hi;
            unpack2(acc[i][j], lo, hi);
            float s = lo + hi + bias[c];
            if (MODE == 0) s += cvx * wrS[c] + cvy * wrS[128 + c] + cvz * wrS[256 + c];
            else s = fmaxf(s, 0.0f);
            Bout[(n * 64 + ((c >> 1) ^ sw)) * 2 + (c & 1)] = s;
        }
    }
}

__global__ __launch_bounds__(MLP_THREADS, 1) void node_mlp_kernel(
    const float* __restrict__ inp,
    const float* __restrict__ W2, const float* __restrict__ b2,
    const float* __restrict__ Wr, const float* __restrict__ br,
    const float* __restrict__ W3, const float* __restrict__ b3,
    const float* __restrict__ W4, const float* __restrict__ b4,
    const float* __restrict__ W5, const float* __restrict__ b5,
    float* __restrict__ out)
{
    extern __shared__ float sm[];
    int t = threadIdx.x;
    int n0 = blockIdx.x * NT;
    const float inv99 = 1.0f / 99.0f;

    for (int idx = t; idx < NT * 128; idx += MLP_THREADS) {
        int n = idx >> 7, k = idx & 127;
        sm[OFF_A + a_fidx(n, k)] = g_hacc[(size_t)(n0 + n) * 128 + k] * inv99;
    }
    for (int idx = t; idx < 768; idx += MLP_THREADS) {
        int k = idx / 6, j = idx % 6;
        sm[OFF_W5T + j * 128 + k] = W5[idx];
    }
    for (int idx = t; idx < 384; idx += MLP_THREADS) sm[OFF_WR + idx] = Wr[384 + idx];
    if (t < 128) {
        sm[OFF_B2R + t] = b2[t] + br[t];
        sm[OFF_B3 + t] = b3[t];
        sm[OFF_B4 + t] = b4[t];
    }
    if (t < 6) sm[OFF_B5 + t] = b5[t];

    u64* A64 = (u64*)(sm + OFF_A);
    u64* B64 = (u64*)(sm + OFF_B);
    u64* Wt64 = (u64*)(sm + OFF_WT);

    for (int idx = t; idx < 16384; idx += MLP_THREADS) {
        int k = idx >> 7, c = idx & 127;
        sm[OFF_WT + (c * 64 + ((k >> 1) ^ ((c >> 2) & 7))) * 2 + (k & 1)] = W2[idx];
    }
    __syncthreads();
    gemm_layer<0>(A64, sm + OFF_B, Wt64, sm + OFF_B2R, n0, sm + OFF_WR);
    __syncthreads();

    for (int idx = t; idx < 16384; idx += MLP_THREADS) {
        int k = idx >> 7, c = idx & 127;
        sm[OFF_WT + (c * 64 + ((k >> 1) ^ ((c >> 2) & 7))) * 2 + (k & 1)] = W3[idx];
    }
    __syncthreads();
    gemm_layer<1>(B64, sm + OFF_A, Wt64, sm + OFF_B3, n0, nullptr);
    __syncthreads();

    for (int idx = t; idx < 16384; idx += MLP_THREADS) {
        int k = idx >> 7, c = idx & 127;
        sm[OFF_WT + (c * 64 + ((k >> 1) ^ ((c >> 2) & 7))) * 2 + (k & 1)] = W4[idx];
    }
    __syncthreads();
    gemm_layer<1>(A64, sm + OFF_B, Wt64, sm + OFF_B4, n0, nullptr);
    __syncthreads();

    if (t < NT) {
        int gnode = n0 + t;
        if (gnode < NODES) {
            int sw = (t >> 3) & 3;
            const u64* Pp = B64 + t * 64;
            u64 sj2[6];
#pragma unroll
            for (int j = 0; j < 6; j++) sj2[j] = 0ull;
#pragma unroll 8
            for (int kp = 0; kp < 64; kp++) {
                u64 x2 = Pp[kp ^ sw];
#pragma unroll
                for (int j = 0; j < 6; j++) {
                    u64 w2 = *(const u64*)&sm[OFF_W5T + j * 128 + 2 * kp];
                    sj2[j] = fma2(x2, w2, sj2[j]);
                }
            }
            float pred[6];
#pragma unroll
            for (int j = 0; j < 6; j++) {
                float lo, hi;
                unpack2(sj2[j], lo, hi);
                pred[j] = lo + hi + sm[OFF_B5 + j];
            }
            const float* R = g_R + (size_t)gnode * 9;
            float Rl[9];
#pragma unroll
            for (int i = 0; i < 9; i++) Rl[i] = R[i];
            const float* xin = inp + (size_t)gnode * 6;
            float* xout = out + (size_t)gnode * 6;
#pragma unroll
            for (int j = 0; j < 6; j++) {
                int i = j % 3, off = (j / 3) * 3;
                float gl = Rl[i * 3 + 0] * pred[off + 0]
                         + Rl[i * 3 + 1] * pred[off + 1]
                         + Rl[i * 3 + 2] * pred[off + 2];
                xout[j] = xin[j] + gl;
            }
        }
    }
}

// ---------------------------------------------------------------------------
extern "C" void kernel_launch(void* const* d_in, const int* in_sizes, int n_in,
                              void* d_out, int out_size)
{
    const float* inp = (const float*)d_in[0];
    const float* W1  = (const float*)d_in[1];
    const float* b1  = (const float*)d_in[2];
    const float* W2  = (const float*)d_in[3];
    const float* b2  = (const float*)d_in[4];
    const float* Wr  = (const float*)d_in[5];
    const float* br  = (const float*)d_in[6];
    const float* W3  = (const float*)d_in[7];
    const float* b3  = (const float*)d_in[8];
    const float* W4  = (const float*)d_in[9];
    const float* b4  = (const float*)d_in[10];
    const float* W5  = (const float*)d_in[11];
    const float* b5  = (const float*)d_in[12];
    float* out = (float*)d_out;

    const int SMEM3 = SMEM_FL * 4;
    cudaFuncSetAttribute(node_mlp_kernel,
                         cudaFuncAttributeMaxDynamicSharedMemorySize, SMEM3);

    node_pre_kernel<<<NODES / 128, 128>>>(inp);
    edge_hmma_kernel<<<EBLOCKS, 128>>>(inp, W1, b1);
    node_mlp_kernel<<<MLP_BLOCKS, MLP_THREADS, SMEM3>>>(inp, W2, b2, Wr, br,
                                                        W3, b3, W4, b4, W5, b5, out);
}